// round 16
// baseline (speedup 1.0000x reference)
#include <cuda_runtime.h>
#include <cuda_fp16.h>
#include <math_constants.h>
#include <cstdint>

#define B_ 32
#define C_ 273
#define T_ 4096
#define O_ 270
#define D_ 288
#define WSTRD 320                        // g_w row stride (halves)

// Device scratch (allocation-free rule: __device__ globals)
__device__ __half g_emb[B_ * C_ * D_];       // [B][C][288] fp16
__device__ __half g_h[288 * 288];            // heads fp16, zero-padded rows 270..287
__device__ __half g_w[B_ * 288 * WSTRD];     // [B][288][320] fp16, zero padded
__device__ float g_s[B_ * 6 * 2 * 48 * 288]; // split-D partial scores, 2 slots
__device__ int g_cnt[B_ * 6];                // arrival counters (self-resetting)

__device__ __forceinline__ uint32_t smem_u32(const void* p) {
    uint32_t a;
    asm("{ .reg .u64 t; cvta.to.shared.u64 t, %1; cvt.u32.u64 %0, t; }"
        : "=r"(a) : "l"(p));
    return a;
}

#define CP16(dst, src) \
    asm volatile("cp.async.cg.shared.global [%0], [%1], 16;" \
                 :: "r"(dst), "l"(src) : "memory")
#define CP16Z(dst, src, ssz) \
    asm volatile("cp.async.cg.shared.global [%0], [%1], 16, %2;" \
                 :: "r"(dst), "l"(src), "r"(ssz) : "memory")
#define CP_COMMIT() asm volatile("cp.async.commit_group;" ::: "memory")
#define CP_WAIT(n)  asm volatile("cp.async.wait_group %0;" :: "n"(n) : "memory")

#define LDSM4(r, addr) \
    asm volatile("ldmatrix.sync.aligned.m8n8.x4.shared.b16 {%0,%1,%2,%3}, [%4];" \
        : "=r"((r)[0]), "=r"((r)[1]), "=r"((r)[2]), "=r"((r)[3]) : "r"(addr))
#define LDSM4T(r, addr) \
    asm volatile("ldmatrix.sync.aligned.m8n8.x4.trans.shared.b16 {%0,%1,%2,%3}, [%4];" \
        : "=r"((r)[0]), "=r"((r)[1]), "=r"((r)[2]), "=r"((r)[3]) : "r"(addr))

#define MMA_F16(d, a, b) \
    asm volatile("mma.sync.aligned.m16n8k16.row.col.f32.f16.f16.f32 " \
        "{%0,%1,%2,%3}, {%4,%5,%6,%7}, {%8,%9}, {%0,%1,%2,%3};" \
        : "+f"((d)[0]), "+f"((d)[1]), "+f"((d)[2]), "+f"((d)[3]) \
        : "r"((a)[0]), "r"((a)[1]), "r"((a)[2]), "r"((a)[3]), \
          "r"((b)[0]), "r"((b)[1]))

// ---------------------------------------------------------------------------
// Kernel 1: Fourier embedding via angle addition + heads prep in grid tail.
// ---------------------------------------------------------------------------
#define EMB_BLOCKS ((B_ * C_) / 4)              // 2184 (8736 warps)
#define HEADS_BLOCKS ((288 * 288) / 128)        // 648

__global__ void __launch_bounds__(128) emb_kernel(const float* __restrict__ pos,
                                                  const float* __restrict__ heads) {
    int blk = blockIdx.x;
    int tid = threadIdx.x;
    if (blk >= EMB_BLOCKS) {
        int idx = (blk - EMB_BLOCKS) * 128 + tid;   // 0 .. 82943
        int row = idx / 288, col = idx - row * 288;
        float v = (row < O_) ? heads[row * D_ + col] : 0.f;
        g_h[row * 288 + col] = __float2half_rn(v);
        return;
    }
    int wid = tid >> 5, lane = tid & 31;
    int bc = blk * 4 + wid;
    float px = pos[bc * 2 + 0] + 0.1f;
    float py = pos[bc * 2 + 1] + 0.1f;
    const float sc = 6.283185307179586f / 1.2f;

    float ang = 0.f;
    if (lane < 12)      ang = px * (sc * (float)lane);
    else if (lane < 24) ang = py * (sc * (float)(lane - 12));
    float s, c;
    __sincosf(ang, &s, &c);

    __half* eo = g_emb + (size_t)bc * D_;
#pragma unroll
    for (int j = 0; j < 5; j++) {
        int i = lane + 32 * j;
        int fx = i / 12, fy = i - fx * 12;
        float cX = __shfl_sync(0xffffffffu, c, fx);
        float sX = __shfl_sync(0xffffffffu, s, fx);
        float cY = __shfl_sync(0xffffffffu, c, 12 + fy);
        float sY = __shfl_sync(0xffffffffu, s, 12 + fy);
        if (i < 144) {
            eo[i] = __float2half_rn(cX * cY - sX * sY);
            eo[144 + i] = __float2half_rn(sX * cY + cX * sY);
        }
    }
}

// ---------------------------------------------------------------------------
// Kernel 2: SPLIT-D scores GEMM (fp16 m16n8k16) + last-arriver softmax.
// Grid (6 o-tiles, 2 D-halves, 32 b). Each CTA: 48o x 288c over D-half (144,
// 3 chunks of 48). Partial -> g_s slot; second arriver adds peer (+__ldcg)
// and runs softmax -> g_w fp16. fp32 add is commutative => deterministic.
// ---------------------------------------------------------------------------
#define SH2 56     // smem stride in halves (112B rows -> ldsm conflict-free)
#define SS_STR 292
#define H_STG (48 * SH2 * 2)    // 5376 B per heads stage
#define E_STG (288 * SH2 * 2)   // 32256 B per emb stage

__global__ void __launch_bounds__(192) scores_fused(
        const unsigned char* __restrict__ mask) {
    extern __shared__ __half ssm2[];
    __half* sH = ssm2;                      // [2][48][56]
    __half* sE = ssm2 + 2 * 48 * SH2;       // [2][288][56]
    float* sS = (float*)(ssm2 + 2 * 48 * SH2);   // overlay after GEMM: [48][292]
    uint32_t sHb = smem_u32(sH), sEb = smem_u32(sE);

    int tid = threadIdx.x;
    int wid = tid >> 5, lane = tid & 31;
    int wn = wid;                          // 0..5
    int lq = lane >> 2, lr = lane & 3;
    int ot = blockIdx.x;
    int dh = blockIdx.y;                   // D-half 0/1
    int b = blockIdx.z;
    int o0 = ot * 48;
    int dbase = dh * 144;

    const __half* embb = g_emb + (size_t)b * C_ * D_;

    uint32_t frow = (uint32_t)(lane & 15);
    uint32_t fksel = (uint32_t)((lane >> 4) * 8);

    float acc[3][6][4];
#pragma unroll
    for (int i = 0; i < 3; i++)
#pragma unroll
        for (int j = 0; j < 6; j++)
#pragma unroll
            for (int r = 0; r < 4; r++) acc[i][j][r] = 0.f;

    auto load_chunk = [&](int ch) {
        int d0 = dbase + ch * 48;
        int st = ch & 1;
        uint32_t hdst = sHb + st * H_STG;
        uint32_t edst = sEb + st * E_STG;
#pragma unroll
        for (int it = 0; it < 2; it++) {    // heads: 48 rows x 6 units = 288
            int idx = tid + it * 192;
            if (idx < 288) {
                int row = idx / 6, qq = idx - row * 6;
                CP16(hdst + (uint32_t)(row * (SH2 * 2) + qq * 16),
                     g_h + (size_t)(o0 + row) * 288 + d0 + qq * 8);
            }
        }
#pragma unroll
        for (int it = 0; it < 9; it++) {    // emb: 288 rows x 6 units = 1728
            int idx = tid + it * 192;
            int row = idx / 6, qq = idx - row * 6;
            const __half* src = embb + (size_t)(row < C_ ? row : 0) * D_ + d0 + qq * 8;
            CP16Z(edst + (uint32_t)(row * (SH2 * 2) + qq * 16), src,
                  (row < C_) ? 16 : 0);
        }
        CP_COMMIT();
    };

    load_chunk(0);
    for (int ch = 0; ch < 3; ch++) {
        if (ch + 1 < 3) { load_chunk(ch + 1); CP_WAIT(1); }
        else            { CP_WAIT(0); }
        __syncthreads();

        int st = ch & 1;
        uint32_t hbase = sHb + st * H_STG;
        uint32_t ebase = sEb + st * E_STG;

#pragma unroll
        for (int ks = 0; ks < 3; ks++) {
            uint32_t afr[3][4];
#pragma unroll
            for (int mt = 0; mt < 3; mt++)
                LDSM4(afr[mt], hbase + (uint32_t)(mt * 16 + frow) * (SH2 * 2)
                               + (ks * 16 + fksel) * 2);
            uint32_t bfr[3][4];
#pragma unroll
            for (int nb = 0; nb < 3; nb++)
                LDSM4(bfr[nb], ebase + (uint32_t)(wn * 48 + nb * 16 + frow) * (SH2 * 2)
                               + (ks * 16 + fksel) * 2);
#pragma unroll
            for (int mt = 0; mt < 3; mt++)
#pragma unroll
                for (int nt = 0; nt < 6; nt++) {
                    uint32_t bp[2] = { bfr[nt >> 1][nt & 1],
                                       bfr[nt >> 1][2 + (nt & 1)] };
                    MMA_F16(acc[mt][nt], afr[mt], bp);
                }
        }
        __syncthreads();
    }

    // acc -> smem sS AND own g_s slot
    int slot_id = b * 6 + ot;
    float* own = g_s + ((size_t)slot_id * 2 + dh) * (48 * 288);
#pragma unroll
    for (int mt = 0; mt < 3; mt++)
#pragma unroll
        for (int half = 0; half < 2; half++) {
            int row = mt * 16 + lq + half * 8;
            float* sp = sS + (size_t)row * SS_STR + wn * 48 + lr * 2;
            float* gp = own + (size_t)row * 288 + wn * 48 + lr * 2;
#pragma unroll
            for (int nt = 0; nt < 6; nt++) {
                float2 v = make_float2(acc[mt][nt][half * 2],
                                       acc[mt][nt][half * 2 + 1]);
                *(float2*)(sp + nt * 8) = v;
                *(float2*)(gp + nt * 8) = v;
            }
        }
    __threadfence();
    __shared__ int s_old;
    __syncthreads();
    if (tid == 0) s_old = atomicAdd(&g_cnt[slot_id], 1);
    __syncthreads();
    if (s_old == 0) return;                 // first arriver exits
    if (tid == 0) atomicExch(&g_cnt[slot_id], 0);   // reset for next replay

    // add peer partial into sS (L2-coherent loads)
    const float* peer = g_s + ((size_t)slot_id * 2 + (1 - dh)) * (48 * 288);
    for (int i = tid; i < 48 * 288; i += 192) {
        int row = i / 288, col = i - row * 288;
        sS[(size_t)row * SS_STR + col] += __ldcg(peer + i);
    }
    __syncthreads();

    // row softmax: warp wid handles rows wid*8 .. wid*8+7
    const unsigned char* mrow = mask + (size_t)b * C_;
#pragma unroll
    for (int j = 0; j < 8; j++) {
        int r = wid * 8 + j;
        int og = o0 + r;
        bool dead = (og >= O_);
        const float* srow = sS + (size_t)r * SS_STR;
        float v[9];
        float mx = -CUDART_INF_F;
#pragma unroll
        for (int i = 0; i < 9; i++) {
            int c = lane + 32 * i;
            v[i] = (c < C_ && !mrow[c]) ? srow[c] : -CUDART_INF_F;
            mx = fmaxf(mx, v[i]);
        }
#pragma unroll
        for (int off = 16; off; off >>= 1)
            mx = fmaxf(mx, __shfl_xor_sync(0xffffffffu, mx, off));
        float sum = 0.f;
#pragma unroll
        for (int i = 0; i < 9; i++) {
            v[i] = __expf(v[i] - mx);
            sum += v[i];
        }
#pragma unroll
        for (int off = 16; off; off >>= 1)
            sum += __shfl_xor_sync(0xffffffffu, sum, off);
        float inv = 1.f / sum;
        __half* wout = g_w + ((size_t)b * 288 + og) * WSTRD;
#pragma unroll
        for (int i = 0; i < 9; i++) {
            int c = lane + 32 * i;
            float hv = (!dead && c < C_) ? v[i] * inv : 0.f;
            wout[c] = __float2half_rn(hv);
        }
        wout[lane + 288] = __float2half_rn(0.f);   // zero pad cols 288..319
    }
}

// ---------------------------------------------------------------------------
// Kernel 3: fp16 mma.sync merge GEMM, meg-resident, K=288 EXACT. (R14 proven)
// One CTA per (b, t0=128); 8 warps 2(m) x 4(n); warp tile 48x32.
// W double-buffered [96x64] stages; meg streamed during o-tile 0 (STS@ks2).
// ---------------------------------------------------------------------------
#define BT 128
#define MSTR 136                         // halves; 272B rows -> ldsm.t conflict-free
#define WSTR 72                          // halves; 144B rows -> ldsm conflict-free
#define WSTG (96 * WSTR * 2)             // 13824 B per W stage
#define MERGE_SMEM (2 * WSTG + 288 * MSTR * 2)   // 27648 + 78336 = 105984

__global__ void __launch_bounds__(256, 2) merge_mma(
        const float* __restrict__ meg,
        float* __restrict__ out) {
    extern __shared__ __half smh[];
    __half* sW = smh;                        // [2][96][WSTR]
    __half* sMeg = smh + 2 * 96 * WSTR;      // [288][MSTR]
    uint32_t sWb = smem_u32(sW), sMb = smem_u32(sMeg);

    int tid = threadIdx.x;
    int wid = tid >> 5, lane = tid & 31;
    int wm = wid >> 2, wn = wid & 3;
    int lq = lane >> 2, lr = lane & 3;
    int t0 = blockIdx.x * BT;
    int b = blockIdx.y;

    const float* megb = meg + (size_t)b * C_ * T_;
    const __half* wbg = g_w + (size_t)b * 288 * WSTRD;

    uint32_t a_row = (uint32_t)(wm * 48 + (lane & 15));
    uint32_t a_ksel = (uint32_t)((lane >> 4) * 8);
    uint32_t b_row = (uint32_t)(lane & 15);
    uint32_t b_nsel = (uint32_t)(wn * 32 + (lane >> 4) * 8);

    auto loadW = [&](int q) {
        if (q < 15) {
            int ot = q / 5, ch = q - ot * 5;
            const __half* wb = wbg + (size_t)(ot * 96) * WSTRD + ch * 64;
            uint32_t wdst = sWb + (uint32_t)(q & 1) * WSTG;
#pragma unroll
            for (int it = 0; it < 3; it++) {
                int idx = tid + it * 256;       // 0..767
                int row = idx >> 3, qq = idx & 7;
                CP16(wdst + (uint32_t)(row * (WSTR * 2) + qq * 16),
                     wb + (size_t)row * WSTRD + qq * 8);
            }
        }
        CP_COMMIT();
    };

    int m_row = tid >> 5;                   // 0..7, row stride 8
    int m_q = tid & 31;                     // f4 col
    auto loadM = [&](int ch, float4* v) {
        int c0 = ch * 64;
#pragma unroll
        for (int it = 0; it < 8; it++) {
            int c = c0 + m_row + it * 8;
            if (c < C_)
                v[it] = *(const float4*)(megb + (size_t)c * T_ + t0 + (m_q << 2));
            else
                v[it] = make_float4(0.f, 0.f, 0.f, 0.f);
        }
    };
    auto stsM = [&](int ch, const float4* v) {
#pragma unroll
        for (int it = 0; it < 8; it++) {
            int row = ch * 64 + m_row + it * 8;
            if (row < 288) {
                __half2 h01 = __floats2half2_rn(v[it].x, v[it].y);
                __half2 h23 = __floats2half2_rn(v[it].z, v[it].w);
                uint2 u;
                u.x = *(uint32_t*)&h01;
                u.y = *(uint32_t*)&h23;
                *(uint2*)(sMeg + (size_t)row * MSTR + (m_q << 2)) = u;
            }
        }
    };

    float4 vreg[8];
    loadW(0);
    loadM(0, vreg);
    stsM(0, vreg);

    float acc[3][4][4];
#pragma unroll
    for (int i = 0; i < 3; i++)
#pragma unroll
        for (int j = 0; j < 4; j++)
#pragma unroll
            for (int r = 0; r < 4; r++) acc[i][j][r] = 0.f;

    for (int q = 0; q < 15; q++) {
        bool stream = (q < 4);
        if (stream) loadM(q + 1, vreg);
        CP_WAIT(0);
        __syncthreads();
        loadW(q + 1);

        uint32_t wbase = sWb + (uint32_t)(q & 1) * WSTG;
        int cq = q % 5;
        int kc = cq * 64;
        int nks = (cq == 4) ? 2 : 4;

#pragma unroll
        for (int ks = 0; ks < 4; ks++) {
            if (ks >= nks) break;
            uint32_t afr[3][4];
#pragma unroll
            for (int mt = 0; mt < 3; mt++)
                LDSM4(afr[mt], wbase + (a_row + mt * 16) * (WSTR * 2)
                               + (ks * 16 + a_ksel) * 2);
            uint32_t bfr[2][4];
#pragma unroll
            for (int ldm = 0; ldm < 2; ldm++)
                LDSM4T(bfr[ldm], sMb + (uint32_t)(kc + ks * 16 + b_row) * (MSTR * 2)
                                 + (b_nsel + ldm * 16) * 2);
#pragma unroll
            for (int mt = 0; mt < 3; mt++)
#pragma unroll
                for (int nt = 0; nt < 4; nt++)
                    MMA_F16(acc[mt][nt], afr[mt], &bfr[nt >> 1][(nt & 1) * 2]);
            if (ks == 2 && stream) stsM(q + 1, vreg);
        }

        if (cq == 4) {
            int o0 = (q / 5) * 96;
#pragma unroll
            for (int mt = 0; mt < 3; mt++) {
#pragma unroll
                for (int half = 0; half < 2; half++) {
                    int og = o0 + wm * 48 + mt * 16 + lq + half * 8;
                    if (og < O_) {
                        float* op = out + ((size_t)b * O_ + og) * T_
                                    + t0 + wn * 32 + lr * 2;
#pragma unroll
                        for (int nt = 0; nt < 4; nt++) {
                            float2 v = make_float2(acc[mt][nt][half * 2],
                                                   acc[mt][nt][half * 2 + 1]);
                            *(float2*)(op + nt * 8) = v;
                        }
                    }
                }
            }
#pragma unroll
            for (int i = 0; i < 3; i++)
#pragma unroll
                for (int j = 0; j < 4; j++)
#pragma unroll
                    for (int r = 0; r < 4; r++) acc[i][j][r] = 0.f;
        }
    }
}

// ---------------------------------------------------------------------------
extern "C" void kernel_launch(void* const* d_in, const int* in_sizes, int n_in,
                              void* d_out, int out_size) {
    const float* meg = (const float*)d_in[0];
    const float* pos = (const float*)d_in[1];
    const float* heads = (const float*)d_in[2];
    const unsigned char* mask = (const unsigned char*)d_in[3];
    float* out = (float*)d_out;

    int smemS = 2 * H_STG + 2 * E_STG;   // 10752 + 64512 = 75264 (sS overlays sE)
    cudaFuncSetAttribute(scores_fused,
                         cudaFuncAttributeMaxDynamicSharedMemorySize, smemS);
    cudaFuncSetAttribute(merge_mma,
                         cudaFuncAttributeMaxDynamicSharedMemorySize, MERGE_SMEM);

    emb_kernel<<<EMB_BLOCKS + HEADS_BLOCKS, 128>>>(pos, heads);
    scores_fused<<<dim3(6, 2, B_), 192, smemS>>>(mask);
    merge_mma<<<dim3(T_ / BT, B_), 256, MERGE_SMEM>>>(meg, out);
}

// round 17
// speedup vs baseline: 1.1001x; 1.1001x over previous
#include <cuda_runtime.h>
#include <cuda_fp16.h>
#include <math_constants.h>
#include <cstdint>

#define B_ 32
#define C_ 273
#define T_ 4096
#define O_ 270
#define D_ 288
#define WSTRD 320                        // g_w row stride (halves)

// Device scratch (allocation-free rule: __device__ globals)
__device__ __half g_emb[B_ * C_ * D_];       // [B][C][288] fp16
__device__ __half g_h[288 * 288];            // heads fp16, zero-padded rows 270..287
__device__ __half g_w[B_ * 288 * WSTRD];     // [B][288][320] fp16, zero padded

__device__ __forceinline__ uint32_t smem_u32(const void* p) {
    uint32_t a;
    asm("{ .reg .u64 t; cvta.to.shared.u64 t, %1; cvt.u32.u64 %0, t; }"
        : "=r"(a) : "l"(p));
    return a;
}

#define CP16(dst, src) \
    asm volatile("cp.async.cg.shared.global [%0], [%1], 16;" \
                 :: "r"(dst), "l"(src) : "memory")
#define CP16Z(dst, src, ssz) \
    asm volatile("cp.async.cg.shared.global [%0], [%1], 16, %2;" \
                 :: "r"(dst), "l"(src), "r"(ssz) : "memory")
#define CP_COMMIT() asm volatile("cp.async.commit_group;" ::: "memory")
#define CP_WAIT(n)  asm volatile("cp.async.wait_group %0;" :: "n"(n) : "memory")

#define LDSM4(r, addr) \
    asm volatile("ldmatrix.sync.aligned.m8n8.x4.shared.b16 {%0,%1,%2,%3}, [%4];" \
        : "=r"((r)[0]), "=r"((r)[1]), "=r"((r)[2]), "=r"((r)[3]) : "r"(addr))
#define LDSM4T(r, addr) \
    asm volatile("ldmatrix.sync.aligned.m8n8.x4.trans.shared.b16 {%0,%1,%2,%3}, [%4];" \
        : "=r"((r)[0]), "=r"((r)[1]), "=r"((r)[2]), "=r"((r)[3]) : "r"(addr))

#define MMA_F16(d, a, b) \
    asm volatile("mma.sync.aligned.m16n8k16.row.col.f32.f16.f16.f32 " \
        "{%0,%1,%2,%3}, {%4,%5,%6,%7}, {%8,%9}, {%0,%1,%2,%3};" \
        : "+f"((d)[0]), "+f"((d)[1]), "+f"((d)[2]), "+f"((d)[3]) \
        : "r"((a)[0]), "r"((a)[1]), "r"((a)[2]), "r"((a)[3]), \
          "r"((b)[0]), "r"((b)[1]))

// ---------------------------------------------------------------------------
// Kernel 1: Fourier embedding via angle addition + heads prep in grid tail.
// ---------------------------------------------------------------------------
#define EMB_BLOCKS ((B_ * C_) / 4)              // 2184 (8736 warps)
#define HEADS_BLOCKS ((288 * 288) / 128)        // 648

__global__ void __launch_bounds__(128) emb_kernel(const float* __restrict__ pos,
                                                  const float* __restrict__ heads) {
    int blk = blockIdx.x;
    int tid = threadIdx.x;
    if (blk >= EMB_BLOCKS) {
        int idx = (blk - EMB_BLOCKS) * 128 + tid;   // 0 .. 82943
        int row = idx / 288, col = idx - row * 288;
        float v = (row < O_) ? heads[row * D_ + col] : 0.f;
        g_h[row * 288 + col] = __float2half_rn(v);
        return;
    }
    int wid = tid >> 5, lane = tid & 31;
    int bc = blk * 4 + wid;
    float px = pos[bc * 2 + 0] + 0.1f;
    float py = pos[bc * 2 + 1] + 0.1f;
    const float sc = 6.283185307179586f / 1.2f;

    float ang = 0.f;
    if (lane < 12)      ang = px * (sc * (float)lane);
    else if (lane < 24) ang = py * (sc * (float)(lane - 12));
    float s, c;
    __sincosf(ang, &s, &c);

    __half* eo = g_emb + (size_t)bc * D_;
#pragma unroll
    for (int j = 0; j < 5; j++) {
        int i = lane + 32 * j;
        int fx = i / 12, fy = i - fx * 12;
        float cX = __shfl_sync(0xffffffffu, c, fx);
        float sX = __shfl_sync(0xffffffffu, s, fx);
        float cY = __shfl_sync(0xffffffffu, c, 12 + fy);
        float sY = __shfl_sync(0xffffffffu, s, 12 + fy);
        if (i < 144) {
            eo[i] = __float2half_rn(cX * cY - sX * sY);
            eo[144 + i] = __float2half_rn(sX * cY + cX * sY);
        }
    }
}

// ---------------------------------------------------------------------------
// Kernel 2: fused scores GEMM (fp16 m16n8k16) + row softmax -> g_w fp16.
// CTA = 48 o-rows x full 288 c, per b. 6 warps (192 thr), warp tile 48x48.
// BK=48 -> 6 chunk-rounds (was 9 @ BK=32): fewer serial rendezvous.
// ---------------------------------------------------------------------------
#define SH2 56     // smem stride in halves (112B rows -> ldsm conflict-free)
#define SS_STR 292
#define H_STG (48 * SH2 * 2)    // 5376 B per heads stage
#define E_STG (288 * SH2 * 2)   // 32256 B per emb stage

__global__ void __launch_bounds__(192) scores_fused(
        const unsigned char* __restrict__ mask) {
    extern __shared__ __half ssm2[];
    __half* sH = ssm2;                      // [2][48][56]
    __half* sE = ssm2 + 2 * 48 * SH2;       // [2][288][56]
    float* sS = (float*)(ssm2 + 2 * 48 * SH2);   // overlay after GEMM: [48][292]
    uint32_t sHb = smem_u32(sH), sEb = smem_u32(sE);

    int tid = threadIdx.x;
    int wid = tid >> 5, lane = tid & 31;
    int wn = wid;                          // 0..5
    int lq = lane >> 2, lr = lane & 3;
    int o0 = blockIdx.x * 48;
    int b = blockIdx.y;

    const __half* embb = g_emb + (size_t)b * C_ * D_;

    uint32_t frow = (uint32_t)(lane & 15);
    uint32_t fksel = (uint32_t)((lane >> 4) * 8);

    float acc[3][6][4];
#pragma unroll
    for (int i = 0; i < 3; i++)
#pragma unroll
        for (int j = 0; j < 6; j++)
#pragma unroll
            for (int r = 0; r < 4; r++) acc[i][j][r] = 0.f;

    auto load_chunk = [&](int ch) {
        int d0 = ch * 48;
        int st = ch & 1;
        uint32_t hdst = sHb + st * H_STG;
        uint32_t edst = sEb + st * E_STG;
#pragma unroll
        for (int it = 0; it < 2; it++) {    // heads: 48 rows x 6 units = 288
            int idx = tid + it * 192;
            if (idx < 288) {
                int row = idx / 6, qq = idx - row * 6;
                CP16(hdst + (uint32_t)(row * (SH2 * 2) + qq * 16),
                     g_h + (size_t)(o0 + row) * 288 + d0 + qq * 8);
            }
        }
#pragma unroll
        for (int it = 0; it < 9; it++) {    // emb: 288 rows x 6 units = 1728
            int idx = tid + it * 192;
            int row = idx / 6, qq = idx - row * 6;
            const __half* src = embb + (size_t)(row < C_ ? row : 0) * D_ + d0 + qq * 8;
            CP16Z(edst + (uint32_t)(row * (SH2 * 2) + qq * 16), src,
                  (row < C_) ? 16 : 0);
        }
        CP_COMMIT();
    };

    load_chunk(0);
    for (int ch = 0; ch < 6; ch++) {
        if (ch + 1 < 6) { load_chunk(ch + 1); CP_WAIT(1); }
        else            { CP_WAIT(0); }
        __syncthreads();

        int st = ch & 1;
        uint32_t hbase = sHb + st * H_STG;
        uint32_t ebase = sEb + st * E_STG;

#pragma unroll
        for (int ks = 0; ks < 3; ks++) {
            uint32_t afr[3][4];
#pragma unroll
            for (int mt = 0; mt < 3; mt++)
                LDSM4(afr[mt], hbase + (uint32_t)(mt * 16 + frow) * (SH2 * 2)
                               + (ks * 16 + fksel) * 2);
            uint32_t bfr[3][4];
#pragma unroll
            for (int nb = 0; nb < 3; nb++)
                LDSM4(bfr[nb], ebase + (uint32_t)(wn * 48 + nb * 16 + frow) * (SH2 * 2)
                               + (ks * 16 + fksel) * 2);
#pragma unroll
            for (int mt = 0; mt < 3; mt++)
#pragma unroll
                for (int nt = 0; nt < 6; nt++) {
                    uint32_t bp[2] = { bfr[nt >> 1][nt & 1],
                                       bfr[nt >> 1][2 + (nt & 1)] };
                    MMA_F16(acc[mt][nt], afr[mt], bp);
                }
        }
        __syncthreads();
    }

    // acc -> smem scores [48][292]
#pragma unroll
    for (int mt = 0; mt < 3; mt++)
#pragma unroll
        for (int half = 0; half < 2; half++) {
            int row = mt * 16 + lq + half * 8;
            float* sp = sS + (size_t)row * SS_STR + wn * 48 + lr * 2;
#pragma unroll
            for (int nt = 0; nt < 6; nt++) {
                float2 v = make_float2(acc[mt][nt][half * 2],
                                       acc[mt][nt][half * 2 + 1]);
                *(float2*)(sp + nt * 8) = v;
            }
        }
    __syncthreads();

    // row softmax: warp wid handles rows wid*8 .. wid*8+7
    const unsigned char* mrow = mask + (size_t)b * C_;
#pragma unroll
    for (int j = 0; j < 8; j++) {
        int r = wid * 8 + j;
        int og = o0 + r;
        bool dead = (og >= O_);
        const float* srow = sS + (size_t)r * SS_STR;
        float v[9];
        float mx = -CUDART_INF_F;
#pragma unroll
        for (int i = 0; i < 9; i++) {
            int c = lane + 32 * i;
            v[i] = (c < C_ && !mrow[c]) ? srow[c] : -CUDART_INF_F;
            mx = fmaxf(mx, v[i]);
        }
#pragma unroll
        for (int off = 16; off; off >>= 1)
            mx = fmaxf(mx, __shfl_xor_sync(0xffffffffu, mx, off));
        float sum = 0.f;
#pragma unroll
        for (int i = 0; i < 9; i++) {
            v[i] = __expf(v[i] - mx);
            sum += v[i];
        }
#pragma unroll
        for (int off = 16; off; off >>= 1)
            sum += __shfl_xor_sync(0xffffffffu, sum, off);
        float inv = 1.f / sum;
        __half* wout = g_w + ((size_t)b * 288 + og) * WSTRD;
#pragma unroll
        for (int i = 0; i < 9; i++) {
            int c = lane + 32 * i;
            float hv = (!dead && c < C_) ? v[i] * inv : 0.f;
            wout[c] = __float2half_rn(hv);
        }
        wout[lane + 288] = __float2half_rn(0.f);   // zero pad cols 288..319
    }
}

// ---------------------------------------------------------------------------
// Kernel 3: fp16 mma.sync merge GEMM, meg-resident, K=288 EXACT. (R14 proven)
// One CTA per (b, t0=128); 8 warps 2(m) x 4(n); warp tile 48x32.
// W double-buffered [96x64] stages; meg streamed during o-tile 0 (STS@ks2).
// ---------------------------------------------------------------------------
#define BT 128
#define MSTR 136                         // halves; 272B rows -> ldsm.t conflict-free
#define WSTR 72                          // halves; 144B rows -> ldsm conflict-free
#define WSTG (96 * WSTR * 2)             // 13824 B per W stage
#define MERGE_SMEM (2 * WSTG + 288 * MSTR * 2)   // 27648 + 78336 = 105984

__global__ void __launch_bounds__(256, 2) merge_mma(
        const float* __restrict__ meg,
        float* __restrict__ out) {
    extern __shared__ __half smh[];
    __half* sW = smh;                        // [2][96][WSTR]
    __half* sMeg = smh + 2 * 96 * WSTR;      // [288][MSTR]
    uint32_t sWb = smem_u32(sW), sMb = smem_u32(sMeg);

    int tid = threadIdx.x;
    int wid = tid >> 5, lane = tid & 31;
    int wm = wid >> 2, wn = wid & 3;
    int lq = lane >> 2, lr = lane & 3;
    int t0 = blockIdx.x * BT;
    int b = blockIdx.y;

    const float* megb = meg + (size_t)b * C_ * T_;
    const __half* wbg = g_w + (size_t)b * 288 * WSTRD;

    uint32_t a_row = (uint32_t)(wm * 48 + (lane & 15));
    uint32_t a_ksel = (uint32_t)((lane >> 4) * 8);
    uint32_t b_row = (uint32_t)(lane & 15);
    uint32_t b_nsel = (uint32_t)(wn * 32 + (lane >> 4) * 8);

    auto loadW = [&](int q) {
        if (q < 15) {
            int ot = q / 5, ch = q - ot * 5;
            const __half* wb = wbg + (size_t)(ot * 96) * WSTRD + ch * 64;
            uint32_t wdst = sWb + (uint32_t)(q & 1) * WSTG;
#pragma unroll
            for (int it = 0; it < 3; it++) {
                int idx = tid + it * 256;       // 0..767
                int row = idx >> 3, qq = idx & 7;
                CP16(wdst + (uint32_t)(row * (WSTR * 2) + qq * 16),
                     wb + (size_t)row * WSTRD + qq * 8);
            }
        }
        CP_COMMIT();
    };

    int m_row = tid >> 5;                   // 0..7, row stride 8
    int m_q = tid & 31;                     // f4 col
    auto loadM = [&](int ch, float4* v) {
        int c0 = ch * 64;
#pragma unroll
        for (int it = 0; it < 8; it++) {
            int c = c0 + m_row + it * 8;
            if (c < C_)
                v[it] = *(const float4*)(megb + (size_t)c * T_ + t0 + (m_q << 2));
            else
                v[it] = make_float4(0.f, 0.f, 0.f, 0.f);
        }
    };
    auto stsM = [&](int ch, const float4* v) {
#pragma unroll
        for (int it = 0; it < 8; it++) {
            int row = ch * 64 + m_row + it * 8;
            if (row < 288) {
                __half2 h01 = __floats2half2_rn(v[it].x, v[it].y);
                __half2 h23 = __floats2half2_rn(v[it].z, v[it].w);
                uint2 u;
                u.x = *(uint32_t*)&h01;
                u.y = *(uint32_t*)&h23;
                *(uint2*)(sMeg + (size_t)row * MSTR + (m_q << 2)) = u;
            }
        }
    };

    float4 vreg[8];
    loadW(0);
    loadM(0, vreg);
    stsM(0, vreg);

    float acc[3][4][4];
#pragma unroll
    for (int i = 0; i < 3; i++)
#pragma unroll
        for (int j = 0; j < 4; j++)
#pragma unroll
            for (int r = 0; r < 4; r++) acc[i][j][r] = 0.f;

    for (int q = 0; q < 15; q++) {
        bool stream = (q < 4);
        if (stream) loadM(q + 1, vreg);
        CP_WAIT(0);
        __syncthreads();
        loadW(q + 1);

        uint32_t wbase = sWb + (uint32_t)(q & 1) * WSTG;
        int cq = q % 5;
        int kc = cq * 64;
        int nks = (cq == 4) ? 2 : 4;

#pragma unroll
        for (int ks = 0; ks < 4; ks++) {
            if (ks >= nks) break;
            uint32_t afr[3][4];
#pragma unroll
            for (int mt = 0; mt < 3; mt++)
                LDSM4(afr[mt], wbase + (a_row + mt * 16) * (WSTR * 2)
                               + (ks * 16 + a_ksel) * 2);
            uint32_t bfr[2][4];
#pragma unroll
            for (int ldm = 0; ldm < 2; ldm++)
                LDSM4T(bfr[ldm], sMb + (uint32_t)(kc + ks * 16 + b_row) * (MSTR * 2)
                                 + (b_nsel + ldm * 16) * 2);
#pragma unroll
            for (int mt = 0; mt < 3; mt++)
#pragma unroll
                for (int nt = 0; nt < 4; nt++)
                    MMA_F16(acc[mt][nt], afr[mt], &bfr[nt >> 1][(nt & 1) * 2]);
            if (ks == 2 && stream) stsM(q + 1, vreg);
        }

        if (cq == 4) {
            int o0 = (q / 5) * 96;
#pragma unroll
            for (int mt = 0; mt < 3; mt++) {
#pragma unroll
                for (int half = 0; half < 2; half++) {
                    int og = o0 + wm * 48 + mt * 16 + lq + half * 8;
                    if (og < O_) {
                        float* op = out + ((size_t)b * O_ + og) * T_
                                    + t0 + wn * 32 + lr * 2;
#pragma unroll
                        for (int nt = 0; nt < 4; nt++) {
                            float2 v = make_float2(acc[mt][nt][half * 2],
                                                   acc[mt][nt][half * 2 + 1]);
                            *(float2*)(op + nt * 8) = v;
                        }
                    }
                }
            }
#pragma unroll
            for (int i = 0; i < 3; i++)
#pragma unroll
                for (int j = 0; j < 4; j++)
#pragma unroll
                    for (int r = 0; r < 4; r++) acc[i][j][r] = 0.f;
        }
    }
}

// ---------------------------------------------------------------------------
extern "C" void kernel_launch(void* const* d_in, const int* in_sizes, int n_in,
                              void* d_out, int out_size) {
    const float* meg = (const float*)d_in[0];
    const float* pos = (const float*)d_in[1];
    const float* heads = (const float*)d_in[2];
    const unsigned char* mask = (const unsigned char*)d_in[3];
    float* out = (float*)d_out;

    int smemS = 2 * H_STG + 2 * E_STG;   // 10752 + 64512 = 75264 (sS overlays sE)
    cudaFuncSetAttribute(scores_fused,
                         cudaFuncAttributeMaxDynamicSharedMemorySize, smemS);
    cudaFuncSetAttribute(merge_mma,
                         cudaFuncAttributeMaxDynamicSharedMemorySize, MERGE_SMEM);

    emb_kernel<<<EMB_BLOCKS + HEADS_BLOCKS, 128>>>(pos, heads);
    scores_fused<<<dim3(6, B_), 192, smemS>>>(mask);
    merge_mma<<<dim3(T_ / BT, B_), 256, MERGE_SMEM>>>(meg, out);
}